// round 1
// baseline (speedup 1.0000x reference)
#include <cuda_runtime.h>
#include <math.h>

// Problem constants
#define Bb 4
#define Nn 2048
#define Ff 1024
#define De 128
#define NROWS (Bb*Nn)          // 8192

// Scratch (device globals; no cudaMalloc allowed)
__device__ float g_Q[NROWS * De];
__device__ float g_K[NROWS * De];
__device__ float g_base[(size_t)Bb * Nn * Nn];   // 64 MB
__device__ float g_charges[5 * NROWS];           // c0..c4
__device__ float g_received[4 * NROWS];

// ---------------------------------------------------------------------------
// zero received accumulators
__global__ void zero_recv_kernel() {
    int i = blockIdx.x * blockDim.x + threadIdx.x;
    if (i < 4 * NROWS) g_received[i] = 0.0f;
}

// ---------------------------------------------------------------------------
// Projection GEMM: C[8192 x 128] = A[8192 x 1024] * W[1024 x 128]
// blockIdx.y == 0 -> W_q -> g_Q ; == 1 -> W_k -> g_K
// 128x128 tile, BK=16, 256 threads, 8x8 per thread.
__global__ __launch_bounds__(256) void proj_gemm_kernel(
    const float* __restrict__ A, const float* __restrict__ Wq,
    const float* __restrict__ Wk)
{
    const float* W = (blockIdx.y == 0) ? Wq : Wk;
    float* C = (blockIdx.y == 0) ? g_Q : g_K;

    __shared__ float As[16][128];
    __shared__ float Bs[16][128];

    const int tid = threadIdx.x;
    const int tx = tid & 15;        // 0..15 -> n
    const int ty = tid >> 4;        // 0..15 -> m
    const int mBase = blockIdx.x * 128;

    float acc[8][8];
#pragma unroll
    for (int i = 0; i < 8; i++)
#pragma unroll
        for (int j = 0; j < 8; j++) acc[i][j] = 0.0f;

    for (int k0 = 0; k0 < Ff; k0 += 16) {
        // Load A tile 128x16 (row-major stride 1024), transposed into As[k][m]
#pragma unroll
        for (int l = 0; l < 2; l++) {
            int idx = tid + l * 256;              // 0..511
            int m = idx >> 2;                      // 0..127
            int kq = (idx & 3) * 4;                // 0,4,8,12
            float4 v = *(const float4*)&A[(size_t)(mBase + m) * Ff + k0 + kq];
            As[kq + 0][m] = v.x; As[kq + 1][m] = v.y;
            As[kq + 2][m] = v.z; As[kq + 3][m] = v.w;
        }
        // Load W tile 16x128 (row-major stride 128) into Bs[k][n]
#pragma unroll
        for (int l = 0; l < 2; l++) {
            int idx = tid + l * 256;
            int k = idx >> 5;                      // 0..15
            int n = (idx & 31) * 4;                // 0..124
            *(float4*)&Bs[k][n] = *(const float4*)&W[(size_t)(k0 + k) * De + n];
        }
        __syncthreads();

#pragma unroll
        for (int k = 0; k < 16; k++) {
            float a[8], b[8];
#pragma unroll
            for (int i = 0; i < 8; i++) a[i] = As[k][ty * 8 + i];
#pragma unroll
            for (int j = 0; j < 8; j++) b[j] = Bs[k][tx * 8 + j];
#pragma unroll
            for (int i = 0; i < 8; i++)
#pragma unroll
                for (int j = 0; j < 8; j++) acc[i][j] = fmaf(a[i], b[j], acc[i][j]);
        }
        __syncthreads();
    }

#pragma unroll
    for (int i = 0; i < 8; i++) {
        int m = mBase + ty * 8 + i;
        float4 v0 = make_float4(acc[i][0], acc[i][1], acc[i][2], acc[i][3]);
        float4 v1 = make_float4(acc[i][4], acc[i][5], acc[i][6], acc[i][7]);
        *(float4*)&C[(size_t)m * De + tx * 8 + 0] = v0;
        *(float4*)&C[(size_t)m * De + tx * 8 + 4] = v1;
    }
}

// ---------------------------------------------------------------------------
// Initial charge: c0 = sigmoid(features . charge_w + charge_b)
// one warp per row
__global__ __launch_bounds__(256) void charge0_kernel(
    const float* __restrict__ f, const float* __restrict__ cw,
    const float* __restrict__ cb)
{
    int row = blockIdx.x * 8 + (threadIdx.x >> 5);
    int lane = threadIdx.x & 31;
    const float* fr = f + (size_t)row * Ff;
    float s = 0.0f;
    for (int t = lane; t < Ff; t += 32) s = fmaf(fr[t], cw[t], s);
#pragma unroll
    for (int o = 16; o > 0; o >>= 1) s += __shfl_xor_sync(0xFFFFFFFFu, s, o);
    if (lane == 0) {
        float x = s + cb[0];
        g_charges[row] = 1.0f / (1.0f + __expf(-x));
    }
}

// ---------------------------------------------------------------------------
// compat GEMM: base[b,i,j] = (Q_i . K_j)/sqrt(128) + ls/max(|i-j|,1)
// both operands row-major [2048 x 128] per batch (k contiguous) -> NT gemm
__global__ __launch_bounds__(256) void compat_gemm_kernel(
    const float* __restrict__ ls_p)
{
    const int b = blockIdx.z;
    const float* Qb = g_Q + (size_t)b * Nn * De;
    const float* Kb = g_K + (size_t)b * Nn * De;
    float* Cb = g_base + (size_t)b * Nn * Nn;

    __shared__ float As[16][128];
    __shared__ float Bs[16][128];

    const int tid = threadIdx.x;
    const int tx = tid & 15;
    const int ty = tid >> 4;
    const int iBase = blockIdx.y * 128;
    const int jBase = blockIdx.x * 128;

    float acc[8][8];
#pragma unroll
    for (int i = 0; i < 8; i++)
#pragma unroll
        for (int j = 0; j < 8; j++) acc[i][j] = 0.0f;

    for (int k0 = 0; k0 < De; k0 += 16) {
#pragma unroll
        for (int l = 0; l < 2; l++) {
            int idx = tid + l * 256;
            int m = idx >> 2;
            int kq = (idx & 3) * 4;
            float4 v = *(const float4*)&Qb[(size_t)(iBase + m) * De + k0 + kq];
            As[kq + 0][m] = v.x; As[kq + 1][m] = v.y;
            As[kq + 2][m] = v.z; As[kq + 3][m] = v.w;
        }
#pragma unroll
        for (int l = 0; l < 2; l++) {
            int idx = tid + l * 256;
            int m = idx >> 2;
            int kq = (idx & 3) * 4;
            float4 v = *(const float4*)&Kb[(size_t)(jBase + m) * De + k0 + kq];
            Bs[kq + 0][m] = v.x; Bs[kq + 1][m] = v.y;
            Bs[kq + 2][m] = v.z; Bs[kq + 3][m] = v.w;
        }
        __syncthreads();

#pragma unroll
        for (int k = 0; k < 16; k++) {
            float a[8], bv[8];
#pragma unroll
            for (int i = 0; i < 8; i++) a[i] = As[k][ty * 8 + i];
#pragma unroll
            for (int j = 0; j < 8; j++) bv[j] = Bs[k][tx * 8 + j];
#pragma unroll
            for (int i = 0; i < 8; i++)
#pragma unroll
                for (int j = 0; j < 8; j++) acc[i][j] = fmaf(a[i], bv[j], acc[i][j]);
        }
        __syncthreads();
    }

    const float ls = *ls_p;
    const float rsqrtD = 0.08838834764831845f;  // 1/sqrt(128)
#pragma unroll
    for (int i = 0; i < 8; i++) {
        int gi = iBase + ty * 8 + i;
        float out[8];
#pragma unroll
        for (int j = 0; j < 8; j++) {
            int gj = jBase + tx * 8 + j;
            float dist = fmaxf(fabsf((float)(gi - gj)), 1.0f);
            out[j] = acc[i][j] * rsqrtD + ls / dist;
        }
        *(float4*)&Cb[(size_t)gi * Nn + jBase + tx * 8 + 0] =
            make_float4(out[0], out[1], out[2], out[3]);
        *(float4*)&Cb[(size_t)gi * Nn + jBase + tx * 8 + 4] =
            make_float4(out[4], out[5], out[6], out[7]);
    }
}

// ---------------------------------------------------------------------------
// Softmax pass over logits = base * (1 + ss * sum_{s=1..S} c^s_i c^s_j).
// Computes row softmax; if !WRITE_OUT accumulates column sums into
// g_received[S]; if WRITE_OUT writes the attn matrix to `out`.
// Block: 256 threads, 32 rows. Grid: (64, B).
template<int S, bool WRITE_OUT>
__global__ __launch_bounds__(256) void softmax_pass_kernel(
    float* __restrict__ out, const float* __restrict__ ss_p)
{
    constexpr int SC = (S > 0) ? S : 1;
    __shared__ float s_cj[SC][Nn];
    __shared__ float s_col[Nn];
    __shared__ float s_red[8];

    const int b = blockIdx.y;
    const int rowBase = blockIdx.x * 32;
    const int tid = threadIdx.x;
    const float ss = *ss_p;

#pragma unroll
    for (int s = 0; s < S; s++)
#pragma unroll
        for (int t = 0; t < 8; t++) {
            int j = tid + t * 256;
            s_cj[s][j] = g_charges[(1 + s) * NROWS + b * Nn + j];
        }
    if (!WRITE_OUT)
#pragma unroll
        for (int t = 0; t < 8; t++) s_col[tid + t * 256] = 0.0f;
    __syncthreads();

    for (int r = 0; r < 32; r++) {
        const int i = rowBase + r;
        float ci[SC];
#pragma unroll
        for (int s = 0; s < S; s++)
            ci[s] = g_charges[(1 + s) * NROWS + b * Nn + i] * ss;

        const float* brow = g_base + ((size_t)b * Nn + i) * Nn;

        float lv[8];
        float lmax = -INFINITY;
#pragma unroll
        for (int t = 0; t < 8; t++) {
            int j = tid + t * 256;
            float m = 1.0f;
#pragma unroll
            for (int s = 0; s < S; s++) m = fmaf(ci[s], s_cj[s][j], m);
            float L = brow[j] * m;
            lv[t] = L;
            lmax = fmaxf(lmax, L);
        }
        // block max
#pragma unroll
        for (int o = 16; o > 0; o >>= 1)
            lmax = fmaxf(lmax, __shfl_xor_sync(0xFFFFFFFFu, lmax, o));
        if ((tid & 31) == 0) s_red[tid >> 5] = lmax;
        __syncthreads();
        float rmax = s_red[0];
#pragma unroll
        for (int w = 1; w < 8; w++) rmax = fmaxf(rmax, s_red[w]);

        float lsum = 0.0f;
#pragma unroll
        for (int t = 0; t < 8; t++) {
            float e = __expf(lv[t] - rmax);
            lv[t] = e;
            lsum += e;
        }
        __syncthreads();   // everyone done reading s_red (max)
#pragma unroll
        for (int o = 16; o > 0; o >>= 1)
            lsum += __shfl_xor_sync(0xFFFFFFFFu, lsum, o);
        if ((tid & 31) == 0) s_red[tid >> 5] = lsum;
        __syncthreads();
        float rsum = 0.0f;
#pragma unroll
        for (int w = 0; w < 8; w++) rsum += s_red[w];
        float inv = 1.0f / rsum;

        if (WRITE_OUT) {
            float* orow = out + ((size_t)b * Nn + i) * Nn;
#pragma unroll
            for (int t = 0; t < 8; t++) {
                int j = tid + t * 256;
                orow[j] = lv[t] * inv;
            }
        } else {
#pragma unroll
            for (int t = 0; t < 8; t++) {
                int j = tid + t * 256;
                s_col[j] += lv[t] * inv;
            }
        }
        __syncthreads();   // protect s_red reuse next row
    }

    if (!WRITE_OUT) {
#pragma unroll
        for (int t = 0; t < 8; t++) {
            int j = tid + t * 256;
            atomicAdd(&g_received[S * NROWS + b * Nn + j], s_col[j]);
        }
    }
}

// ---------------------------------------------------------------------------
// charge update: c^{s+1} = c^s * (1 - decay * sigmoid(received_s - 1))
__global__ void charge_update_kernel(int s, const float* __restrict__ decay_p) {
    int r = blockIdx.x * blockDim.x + threadIdx.x;
    if (r >= NROWS) return;
    float recv = g_received[s * NROWS + r];
    float sig = 1.0f / (1.0f + __expf(-(recv - 1.0f)));
    g_charges[(s + 1) * NROWS + r] = g_charges[s * NROWS + r] * (1.0f - (*decay_p) * sig);
}

// ---------------------------------------------------------------------------
extern "C" void kernel_launch(void* const* d_in, const int* in_sizes, int n_in,
                              void* d_out, int out_size)
{
    const float* features = (const float*)d_in[0];
    const float* W_q      = (const float*)d_in[1];
    const float* W_k      = (const float*)d_in[2];
    const float* charge_w = (const float*)d_in[3];
    const float* charge_b = (const float*)d_in[4];
    const float* ls_p     = (const float*)d_in[5];
    const float* ss_p     = (const float*)d_in[6];
    const float* decay_p  = (const float*)d_in[7];
    float* out = (float*)d_out;

    zero_recv_kernel<<<(4 * NROWS + 255) / 256, 256>>>();

    proj_gemm_kernel<<<dim3(NROWS / 128, 2), 256>>>(features, W_q, W_k);
    charge0_kernel<<<NROWS / 8, 256>>>(features, charge_w, charge_b);
    compat_gemm_kernel<<<dim3(Nn / 128, Nn / 128, Bb), 256>>>(ls_p);

    dim3 sgrid(Nn / 32, Bb);

    softmax_pass_kernel<0, false><<<sgrid, 256>>>(nullptr, ss_p);
    charge_update_kernel<<<(NROWS + 255) / 256, 256>>>(0, decay_p);

    softmax_pass_kernel<1, false><<<sgrid, 256>>>(nullptr, ss_p);
    charge_update_kernel<<<(NROWS + 255) / 256, 256>>>(1, decay_p);

    softmax_pass_kernel<2, false><<<sgrid, 256>>>(nullptr, ss_p);
    charge_update_kernel<<<(NROWS + 255) / 256, 256>>>(2, decay_p);

    softmax_pass_kernel<3, false><<<sgrid, 256>>>(nullptr, ss_p);
    charge_update_kernel<<<(NROWS + 255) / 256, 256>>>(3, decay_p);

    softmax_pass_kernel<4, true><<<sgrid, 256>>>(out, ss_p);
}

// round 3
// speedup vs baseline: 1.6845x; 1.6845x over previous
#include <cuda_runtime.h>
#include <cuda_bf16.h>
#include <math.h>
#include <stdint.h>

// Problem constants
#define Bb 4
#define Nn 2048
#define Ff 1024
#define De 128
#define NROWS (Bb*Nn)          // 8192

// ---------------------------------------------------------------------------
// Device global scratch (no cudaMalloc allowed)
__device__ __nv_bfloat16 g_feat_hi[(size_t)NROWS * Ff];
__device__ __nv_bfloat16 g_feat_lo[(size_t)NROWS * Ff];
__device__ __nv_bfloat16 g_WT_hi[2][De * Ff];       // W^T [128 x 1024], [0]=Wq,[1]=Wk
__device__ __nv_bfloat16 g_WT_lo[2][De * Ff];
__device__ __nv_bfloat16 g_QK_hi[2][(size_t)NROWS * De];  // [0]=Q,[1]=K
__device__ __nv_bfloat16 g_QK_lo[2][(size_t)NROWS * De];
__device__ float  g_base[(size_t)Bb * Nn * Nn];     // 64 MB
__device__ float  g_c0[NROWS];
__device__ float4 g_cpack[NROWS];                   // c^1..c^4 packed, zero-padded
__device__ float  g_received[4 * NROWS];

// ---------------------------------------------------------------------------
__device__ __forceinline__ uint32_t smem_u32(const void* p) {
    uint32_t a;
    asm("{ .reg .u64 t; cvta.to.shared.u64 t, %1; cvt.u32.u64 %0, t; }" : "=r"(a) : "l"(p));
    return a;
}
__device__ __forceinline__ uint32_t sw128(uint32_t o) { return o ^ ((o >> 3) & 0x70); }

#define CP_ASYNC16(dst_u32, src_gptr) \
    asm volatile("cp.async.cg.shared.global [%0], [%1], 16;" :: "r"(dst_u32), "l"(src_gptr))
#define CP_COMMIT()  asm volatile("cp.async.commit_group;" ::: "memory")
#define CP_WAIT1()   asm volatile("cp.async.wait_group 1;" ::: "memory")
#define CP_WAIT0()   asm volatile("cp.async.wait_group 0;" ::: "memory")

#define LDMATRIX_X4(r0, r1, r2, r3, addr) \
    asm volatile("ldmatrix.sync.aligned.m8n8.x4.shared.b16 {%0,%1,%2,%3}, [%4];" \
        : "=r"(r0), "=r"(r1), "=r"(r2), "=r"(r3) : "r"(addr))

#define MMA_BF16(acc, a, b0v, b1v) \
    asm volatile("mma.sync.aligned.m16n8k16.row.col.f32.bf16.bf16.f32 " \
        "{%0,%1,%2,%3}, {%4,%5,%6,%7}, {%8,%9}, {%0,%1,%2,%3};" \
        : "+f"((acc)[0]), "+f"((acc)[1]), "+f"((acc)[2]), "+f"((acc)[3]) \
        : "r"((a)[0]), "r"((a)[1]), "r"((a)[2]), "r"((a)[3]), "r"(b0v), "r"(b1v))

// ---------------------------------------------------------------------------
// cp.async one 128x64 bf16 tile (rows of 128B) into SW128-swizzled smem
__device__ __forceinline__ void cpasync_tile(
    uint32_t dst_base, const __nv_bfloat16* src, int strideElems, int tid)
{
#pragma unroll
    for (int u = tid; u < 1024; u += 256) {
        int row = u >> 3, seg = u & 7;
        uint32_t dst = dst_base + sw128((uint32_t)(row * 128 + seg * 16));
        const __nv_bfloat16* g = src + (size_t)row * strideElems + seg * 8;
        CP_ASYNC16(dst, g);
    }
}

// smem buffer layout (per double-buffer slot, 64KB): AH | AL | BH | BL
#define T_AH 0
#define T_AL 16384
#define T_BH 32768
#define T_BL 49152
#define BUF_BYTES 65536
#define GEMM_SMEM (2 * BUF_BYTES)

__device__ __forceinline__ void issue_chunk(
    uint32_t sbuf,
    const __nv_bfloat16* Ah, const __nv_bfloat16* Al, int strideA,
    const __nv_bfloat16* Bh, const __nv_bfloat16* Bl, int strideB,
    int c, int tid)
{
    cpasync_tile(sbuf + T_AH, Ah + c * 64, strideA, tid);
    cpasync_tile(sbuf + T_AL, Al + c * 64, strideA, tid);
    cpasync_tile(sbuf + T_BH, Bh + c * 64, strideB, tid);
    cpasync_tile(sbuf + T_BL, Bl + c * 64, strideB, tid);
    CP_COMMIT();
}

// compute one 64-wide K chunk: 3-term bf16 split accumulate
__device__ __forceinline__ void compute_chunk(uint32_t sbuf, int tid, float acc[4][4][4])
{
    const int lane = tid & 31;
    const int wid = tid >> 5;
    const int wm = wid & 1;        // 2 warps in M
    const int wn = wid >> 1;       // 4 warps in N
    const int q = lane >> 3, r = lane & 7;

    // per-lane ldmatrix address patterns (byte offsets within tile)
    const int a_row = r + ((q & 1) ? 8 : 0);          // + m-tile base
    const int a_colb = ((q & 2) ? 8 : 0) * 2;         // + kb*2
    const int b_row = r + ((q & 2) ? 8 : 0);          // + n-tile base
    const int b_colb = ((q & 1) ? 8 : 0) * 2;

#pragma unroll
    for (int ks = 0; ks < 4; ks++) {
        const int kb2 = ks * 32;                       // kb * 2 bytes

        uint32_t ah[4][4], al[4][4];
#pragma unroll
        for (int mi = 0; mi < 4; mi++) {
            uint32_t off = sw128((uint32_t)((wm * 64 + mi * 16 + a_row) * 128 + kb2 + a_colb));
            LDMATRIX_X4(ah[mi][0], ah[mi][1], ah[mi][2], ah[mi][3], sbuf + T_AH + off);
            LDMATRIX_X4(al[mi][0], al[mi][1], al[mi][2], al[mi][3], sbuf + T_AL + off);
        }
        uint32_t bh[2][4], bl[2][4];
#pragma unroll
        for (int p = 0; p < 2; p++) {
            uint32_t off = sw128((uint32_t)((wn * 32 + p * 16 + b_row) * 128 + kb2 + b_colb));
            LDMATRIX_X4(bh[p][0], bh[p][1], bh[p][2], bh[p][3], sbuf + T_BH + off);
            LDMATRIX_X4(bl[p][0], bl[p][1], bl[p][2], bl[p][3], sbuf + T_BL + off);
        }
#pragma unroll
        for (int mi = 0; mi < 4; mi++)
#pragma unroll
            for (int ni = 0; ni < 4; ni++) {
                const int p = ni >> 1, s = (ni & 1) * 2;
                MMA_BF16(acc[mi][ni], ah[mi], bh[p][s], bh[p][s + 1]);  // hi*hi
                MMA_BF16(acc[mi][ni], ah[mi], bl[p][s], bl[p][s + 1]);  // hi*lo
                MMA_BF16(acc[mi][ni], al[mi], bh[p][s], bh[p][s + 1]);  // lo*hi
            }
    }
}

template<int CHUNKS>
__device__ __forceinline__ void gemm_mainloop(
    const __nv_bfloat16* Ah, const __nv_bfloat16* Al, int strideA,
    const __nv_bfloat16* Bh, const __nv_bfloat16* Bl, int strideB,
    uint32_t sb, int tid, float acc[4][4][4])
{
#pragma unroll
    for (int mi = 0; mi < 4; mi++)
#pragma unroll
        for (int ni = 0; ni < 4; ni++)
#pragma unroll
            for (int k = 0; k < 4; k++) acc[mi][ni][k] = 0.0f;

    issue_chunk(sb, Ah, Al, strideA, Bh, Bl, strideB, 0, tid);

#pragma unroll 1
    for (int c = 0; c < CHUNKS; c++) {
        if (c > 0) __syncthreads();
        if (c + 1 < CHUNKS) {
            issue_chunk(sb + ((c + 1) & 1) * BUF_BYTES, Ah, Al, strideA, Bh, Bl, strideB, c + 1, tid);
            CP_WAIT1();
        } else {
            CP_WAIT0();
        }
        __syncthreads();
        compute_chunk(sb + (c & 1) * BUF_BYTES, tid, acc);
    }
}

// ---------------------------------------------------------------------------
// zero accumulators (received + cpack)
__global__ void zero_kernel() {
    int i = blockIdx.x * blockDim.x + threadIdx.x;
    if (i < 4 * NROWS) g_received[i] = 0.0f;
    else ((float*)g_cpack)[i - 4 * NROWS] = 0.0f;
}

// ---------------------------------------------------------------------------
// fp32 -> (hi, lo) bf16 split for features
__global__ void convert_feat_kernel(const float* __restrict__ f) {
    int i = blockIdx.x * blockDim.x + threadIdx.x;      // over 2M float4s
    float4 v = ((const float4*)f)[i];
    __nv_bfloat16 h0 = __float2bfloat16(v.x), h1 = __float2bfloat16(v.y);
    __nv_bfloat16 h2 = __float2bfloat16(v.z), h3 = __float2bfloat16(v.w);
    __nv_bfloat16 l0 = __float2bfloat16(v.x - __bfloat162float(h0));
    __nv_bfloat16 l1 = __float2bfloat16(v.y - __bfloat162float(h1));
    __nv_bfloat16 l2 = __float2bfloat16(v.z - __bfloat162float(h2));
    __nv_bfloat16 l3 = __float2bfloat16(v.w - __bfloat162float(h3));
    ((__nv_bfloat162*)g_feat_hi)[2 * i]     = __halves2bfloat162(h0, h1);
    ((__nv_bfloat162*)g_feat_hi)[2 * i + 1] = __halves2bfloat162(h2, h3);
    ((__nv_bfloat162*)g_feat_lo)[2 * i]     = __halves2bfloat162(l0, l1);
    ((__nv_bfloat162*)g_feat_lo)[2 * i + 1] = __halves2bfloat162(l2, l3);
}

// transpose + split W (1024x128 -> 128x1024); blockIdx.y: 0=Wq, 1=Wk
__global__ void convert_W_kernel(const float* __restrict__ Wq, const float* __restrict__ Wk) {
    const float* W = (blockIdx.y == 0) ? Wq : Wk;
    int idx = blockIdx.x * blockDim.x + threadIdx.x;    // 0..131071
    int e = idx >> 10, fidx = idx & 1023;
    float x = W[(size_t)fidx * De + e];
    __nv_bfloat16 h = __float2bfloat16(x);
    g_WT_hi[blockIdx.y][idx] = h;
    g_WT_lo[blockIdx.y][idx] = __float2bfloat16(x - __bfloat162float(h));
}

// ---------------------------------------------------------------------------
// Initial charge: c0 = sigmoid(features . charge_w + charge_b); one warp/row
__global__ __launch_bounds__(256) void charge0_kernel(
    const float* __restrict__ f, const float* __restrict__ cw, const float* __restrict__ cb)
{
    int row = blockIdx.x * 8 + (threadIdx.x >> 5);
    int lane = threadIdx.x & 31;
    const float* fr = f + (size_t)row * Ff;
    float s = 0.0f;
    for (int t = lane; t < Ff; t += 32) s = fmaf(fr[t], cw[t], s);
#pragma unroll
    for (int o = 16; o > 0; o >>= 1) s += __shfl_xor_sync(0xFFFFFFFFu, s, o);
    if (lane == 0) g_c0[row] = 1.0f / (1.0f + __expf(-(s + cb[0])));
}

// ---------------------------------------------------------------------------
// Projection GEMM: [128x1024] x [1024x128]^T(K-major) per tile; grid (64, 2)
__global__ __launch_bounds__(256, 1) void proj_mma_kernel() {
    extern __shared__ __align__(1024) char smem[];
    const int tid = threadIdx.x;
    const int y = blockIdx.y;
    const int mBase = blockIdx.x * 128;
    uint32_t sb = smem_u32(smem);

    float acc[4][4][4];
    gemm_mainloop<16>(g_feat_hi + (size_t)mBase * Ff, g_feat_lo + (size_t)mBase * Ff, Ff,
                      g_WT_hi[y], g_WT_lo[y], Ff, sb, tid, acc);

    const int lane = tid & 31, wid = tid >> 5;
    const int wm = wid & 1, wn = wid >> 1;
    const int g = lane >> 2, t2 = (lane & 3) * 2;
    __nv_bfloat16* ph = g_QK_hi[y];
    __nv_bfloat16* pl = g_QK_lo[y];
#pragma unroll
    for (int mi = 0; mi < 4; mi++)
#pragma unroll
        for (int ni = 0; ni < 4; ni++) {
            const int cc = wn * 32 + ni * 8 + t2;
#pragma unroll
            for (int half = 0; half < 2; half++) {
                const int rr = mBase + wm * 64 + mi * 16 + g + half * 8;
                float v0 = acc[mi][ni][half * 2], v1 = acc[mi][ni][half * 2 + 1];
                __nv_bfloat16 h0 = __float2bfloat16(v0), h1 = __float2bfloat16(v1);
                __nv_bfloat16 l0 = __float2bfloat16(v0 - __bfloat162float(h0));
                __nv_bfloat16 l1 = __float2bfloat16(v1 - __bfloat162float(h1));
                *(__nv_bfloat162*)(ph + (size_t)rr * De + cc) = __halves2bfloat162(h0, h1);
                *(__nv_bfloat162*)(pl + (size_t)rr * De + cc) = __halves2bfloat162(l0, l1);
            }
        }
}

// ---------------------------------------------------------------------------
// compat GEMM: base[b,i,j] = Q_i.K_j / sqrt(128) + ls/max(|i-j|,1); grid (16,16,4)
__global__ __launch_bounds__(256, 1) void compat_mma_kernel(const float* __restrict__ ls_p) {
    extern __shared__ __align__(1024) char smem[];
    const int tid = threadIdx.x;
    const int b = blockIdx.z;
    const int iBase = blockIdx.y * 128, jBase = blockIdx.x * 128;
    uint32_t sb = smem_u32(smem);

    float acc[4][4][4];
    gemm_mainloop<2>(g_QK_hi[0] + (size_t)(b * Nn + iBase) * De,
                     g_QK_lo[0] + (size_t)(b * Nn + iBase) * De, De,
                     g_QK_hi[1] + (size_t)(b * Nn + jBase) * De,
                     g_QK_lo[1] + (size_t)(b * Nn + jBase) * De, De, sb, tid, acc);

    const float ls = *ls_p;
    const float rsqrtD = 0.08838834764831845f;  // 1/sqrt(128)
    const int lane = tid & 31, wid = tid >> 5;
    const int wm = wid & 1, wn = wid >> 1;
    const int g = lane >> 2, t2 = (lane & 3) * 2;
#pragma unroll
    for (int mi = 0; mi < 4; mi++)
#pragma unroll
        for (int ni = 0; ni < 4; ni++) {
            const int col = jBase + wn * 32 + ni * 8 + t2;
#pragma unroll
            for (int half = 0; half < 2; half++) {
                const int row = iBase + wm * 64 + mi * 16 + g + half * 8;
                float d0 = fmaxf(fabsf((float)(row - col)), 1.0f);
                float d1 = fmaxf(fabsf((float)(row - col - 1)), 1.0f);
                float2 v;
                v.x = acc[mi][ni][half * 2]     * rsqrtD + __fdividef(ls, d0);
                v.y = acc[mi][ni][half * 2 + 1] * rsqrtD + __fdividef(ls, d1);
                *(float2*)(g_base + ((size_t)(b * Nn + row)) * Nn + col) = v;
            }
        }
}

// ---------------------------------------------------------------------------
// Softmax pass: logits = base * (1 + ss * dot4(c_i, c_j)); g_cpack zero-padded.
// 256 threads, 32 rows/block; each thread owns 8 fixed cols in registers.
template<bool WRITE_OUT>
__global__ __launch_bounds__(256) void softmax_pass_kernel(
    int s, float* __restrict__ out, const float* __restrict__ ss_p)
{
    __shared__ float s_red[2][8];
    const int b = blockIdx.y;
    const int rowBase = blockIdx.x * 32;
    const int tid = threadIdx.x, lane = tid & 31, wid = tid >> 5;
    const float ss = *ss_p;
    const int j0 = tid * 8;

    float4 cj[8];
#pragma unroll
    for (int t = 0; t < 8; t++) cj[t] = g_cpack[b * Nn + j0 + t];

    float col[8];
#pragma unroll
    for (int t = 0; t < 8; t++) col[t] = 0.0f;

    for (int r = 0; r < 32; r++) {
        const int i = rowBase + r;
        float4 ci = g_cpack[b * Nn + i];
        float cx = ci.x * ss, cy = ci.y * ss, cz = ci.z * ss, cw = ci.w * ss;

        const float4* brow = (const float4*)(g_base + ((size_t)(b * Nn + i)) * Nn + j0);
        float4 b0 = brow[0], b1 = brow[1];
        float bb[8] = {b0.x, b0.y, b0.z, b0.w, b1.x, b1.y, b1.z, b1.w};

        float lv[8];
        float lsum = 0.0f;
#pragma unroll
        for (int t = 0; t < 8; t++) {
            float m = 1.0f;
            m = fmaf(cx, cj[t].x, m);
            m = fmaf(cy, cj[t].y, m);
            m = fmaf(cz, cj[t].z, m);
            m = fmaf(cw, cj[t].w, m);
            float e = __expf(bb[t] * m);
            lv[t] = e;
            lsum += e;
        }
#pragma unroll
        for (int o = 16; o > 0; o >>= 1) lsum += __shfl_xor_sync(0xFFFFFFFFu, lsum, o);
        if (lane == 0) s_red[r & 1][wid] = lsum;
        __syncthreads();
        float tot = s_red[r & 1][0];
#pragma unroll
        for (int w = 1; w < 8; w++) tot += s_red[r & 1][w];
        float inv = __fdividef(1.0f, tot);

        if (WRITE_OUT) {
            float4* orow = (float4*)(out + ((size_t)(b * Nn + i)) * Nn + j0);
            orow[0] = make_float4(lv[0] * inv, lv[1] * inv, lv[2] * inv, lv[3] * inv);
            orow[1] = make_float4(lv[4] * inv, lv[5] * inv, lv[6] * inv, lv[7] * inv);
        } else {
#pragma unroll
            for (int t = 0; t < 8; t++) col[t] = fmaf(lv[t], inv, col[t]);
        }
    }
    if (!WRITE_OUT) {
        float* recv = g_received + (size_t)s * NROWS + b * Nn + j0;
#pragma unroll
        for (int t = 0; t < 8; t++) atomicAdd(&recv[t], col[t]);
    }
}

// ---------------------------------------------------------------------------
// charge update: c^{s+1} = c^s * (1 - decay * sigmoid(received_s - 1))
__global__ void charge_update_kernel(int s, const float* __restrict__ decay_p) {
    int r = blockIdx.x * blockDim.x + threadIdx.x;
    if (r >= NROWS) return;
    float recv = g_received[(size_t)s * NROWS + r];
    float prev = (s == 0) ? g_c0[r] : ((float*)&g_cpack[r])[s - 1];
    float sig = 1.0f / (1.0f + __expf(-(recv - 1.0f)));
    ((float*)&g_cpack[r])[s] = prev * (1.0f - (*decay_p) * sig);
}

// ---------------------------------------------------------------------------
extern "C" void kernel_launch(void* const* d_in, const int* in_sizes, int n_in,
                              void* d_out, int out_size)
{
    const float* features = (const float*)d_in[0];
    const float* W_q      = (const float*)d_in[1];
    const float* W_k      = (const float*)d_in[2];
    const float* charge_w = (const float*)d_in[3];
    const float* charge_b = (const float*)d_in[4];
    const float* ls_p     = (const float*)d_in[5];
    const float* ss_p     = (const float*)d_in[6];
    const float* decay_p  = (const float*)d_in[7];
    float* out = (float*)d_out;

    static bool attr_set = false;
    if (!attr_set) {
        cudaFuncSetAttribute(proj_mma_kernel,   cudaFuncAttributeMaxDynamicSharedMemorySize, GEMM_SMEM);
        cudaFuncSetAttribute(compat_mma_kernel, cudaFuncAttributeMaxDynamicSharedMemorySize, GEMM_SMEM);
        attr_set = true;
    }

    zero_kernel<<<(8 * NROWS) / 256, 256>>>();
    convert_feat_kernel<<<((size_t)NROWS * Ff / 4) / 256, 256>>>(features);
    convert_W_kernel<<<dim3((De * Ff) / 256, 2), 256>>>(W_q, W_k);
    charge0_kernel<<<NROWS / 8, 256>>>(features, charge_w, charge_b);

    proj_mma_kernel<<<dim3(NROWS / 128, 2), 256, GEMM_SMEM>>>();
    compat_mma_kernel<<<dim3(Nn / 128, Nn / 128, Bb), 256, GEMM_SMEM>>>(ls_p);

    dim3 sgrid(Nn / 32, Bb);
    for (int s = 0; s < 4; s++) {
        softmax_pass_kernel<false><<<sgrid, 256>>>(s, nullptr, ss_p);
        charge_update_kernel<<<NROWS / 256, 256>>>(s, decay_p);
    }
    softmax_pass_kernel<true><<<sgrid, 256>>>(0, out, ss_p);
}

// round 4
// speedup vs baseline: 1.7260x; 1.0246x over previous
#include <cuda_runtime.h>
#include <cuda_bf16.h>
#include <math.h>
#include <stdint.h>

// Problem constants
#define Bb 4
#define Nn 2048
#define Ff 1024
#define De 128
#define NROWS (Bb*Nn)          // 8192

// ---------------------------------------------------------------------------
// Device global scratch (no cudaMalloc allowed)
__device__ __nv_bfloat16 g_feat_hi[(size_t)NROWS * Ff];
__device__ __nv_bfloat16 g_feat_lo[(size_t)NROWS * Ff];
__device__ __nv_bfloat16 g_WT_hi[2][De * Ff];       // W^T [128 x 1024], [0]=Wq,[1]=Wk
__device__ __nv_bfloat16 g_WT_lo[2][De * Ff];
__device__ __nv_bfloat16 g_QK_hi[2][(size_t)NROWS * De];  // [0]=Q,[1]=K
__device__ __nv_bfloat16 g_QK_lo[2][(size_t)NROWS * De];
__device__ float  g_base[(size_t)Bb * Nn * Nn];     // 64 MB
__device__ float  g_c0[NROWS];
__device__ float4 g_cpack[NROWS];                   // c^1..c^4 packed, zero-padded
__device__ float  g_received[4 * NROWS];

// ---------------------------------------------------------------------------
__device__ __forceinline__ uint32_t smem_u32(const void* p) {
    uint32_t a;
    asm("{ .reg .u64 t; cvta.to.shared.u64 t, %1; cvt.u32.u64 %0, t; }" : "=r"(a) : "l"(p));
    return a;
}
__device__ __forceinline__ uint32_t sw128(uint32_t o) { return o ^ ((o >> 3) & 0x70); }

#define CP_ASYNC16(dst_u32, src_gptr) \
    asm volatile("cp.async.cg.shared.global [%0], [%1], 16;" :: "r"(dst_u32), "l"(src_gptr))
#define CP_COMMIT()  asm volatile("cp.async.commit_group;" ::: "memory")
#define CP_WAIT1()   asm volatile("cp.async.wait_group 1;" ::: "memory")
#define CP_WAIT0()   asm volatile("cp.async.wait_group 0;" ::: "memory")

#define LDMATRIX_X4(r0, r1, r2, r3, addr) \
    asm volatile("ldmatrix.sync.aligned.m8n8.x4.shared.b16 {%0,%1,%2,%3}, [%4];" \
        : "=r"(r0), "=r"(r1), "=r"(r2), "=r"(r3) : "r"(addr))

#define MMA_BF16(acc, a, b0v, b1v) \
    asm volatile("mma.sync.aligned.m16n8k16.row.col.f32.bf16.bf16.f32 " \
        "{%0,%1,%2,%3}, {%4,%5,%6,%7}, {%8,%9}, {%0,%1,%2,%3};" \
        : "+f"((acc)[0]), "+f"((acc)[1]), "+f"((acc)[2]), "+f"((acc)[3]) \
        : "r"((a)[0]), "r"((a)[1]), "r"((a)[2]), "r"((a)[3]), "r"(b0v), "r"(b1v))

// ---------------------------------------------------------------------------
// cp.async one 128x64 bf16 tile (rows of 128B) into SW128-swizzled smem
__device__ __forceinline__ void cpasync_tile(
    uint32_t dst_base, const __nv_bfloat16* src, int strideElems, int tid)
{
#pragma unroll
    for (int u = tid; u < 1024; u += 256) {
        int row = u >> 3, seg = u & 7;
        uint32_t dst = dst_base + sw128((uint32_t)(row * 128 + seg * 16));
        const __nv_bfloat16* g = src + (size_t)row * strideElems + seg * 8;
        CP_ASYNC16(dst, g);
    }
}

// smem buffer layout (per buffer slot, 64KB): AH | AL | BH | BL
#define T_AH 0
#define T_AL 16384
#define T_BH 32768
#define T_BL 49152
#define BUF_BYTES 65536
#define PROJ_SMEM   (3 * BUF_BYTES)   // 3-stage pipeline
#define COMPAT_SMEM (2 * BUF_BYTES)   // both K-chunks resident

__device__ __forceinline__ void issue_chunk(
    uint32_t sbuf,
    const __nv_bfloat16* Ah, const __nv_bfloat16* Al, int strideA,
    const __nv_bfloat16* Bh, const __nv_bfloat16* Bl, int strideB,
    int c, int tid)
{
    cpasync_tile(sbuf + T_AH, Ah + c * 64, strideA, tid);
    cpasync_tile(sbuf + T_AL, Al + c * 64, strideA, tid);
    cpasync_tile(sbuf + T_BH, Bh + c * 64, strideB, tid);
    cpasync_tile(sbuf + T_BL, Bl + c * 64, strideB, tid);
    CP_COMMIT();
}

// compute one 64-wide K chunk: 3-term bf16 split accumulate
__device__ __forceinline__ void compute_chunk(uint32_t sbuf, int tid, float acc[4][4][4])
{
    const int lane = tid & 31;
    const int wid = tid >> 5;
    const int wm = wid & 1;        // 2 warps in M
    const int wn = wid >> 1;       // 4 warps in N
    const int q = lane >> 3, r = lane & 7;

    const int a_row = r + ((q & 1) ? 8 : 0);
    const int a_colb = ((q & 2) ? 8 : 0) * 2;
    const int b_row = r + ((q & 2) ? 8 : 0);
    const int b_colb = ((q & 1) ? 8 : 0) * 2;

#pragma unroll
    for (int ks = 0; ks < 4; ks++) {
        const int kb2 = ks * 32;

        uint32_t ah[4][4], al[4][4];
#pragma unroll
        for (int mi = 0; mi < 4; mi++) {
            uint32_t off = sw128((uint32_t)((wm * 64 + mi * 16 + a_row) * 128 + kb2 + a_colb));
            LDMATRIX_X4(ah[mi][0], ah[mi][1], ah[mi][2], ah[mi][3], sbuf + T_AH + off);
            LDMATRIX_X4(al[mi][0], al[mi][1], al[mi][2], al[mi][3], sbuf + T_AL + off);
        }
        uint32_t bh[2][4], bl[2][4];
#pragma unroll
        for (int p = 0; p < 2; p++) {
            uint32_t off = sw128((uint32_t)((wn * 32 + p * 16 + b_row) * 128 + kb2 + b_colb));
            LDMATRIX_X4(bh[p][0], bh[p][1], bh[p][2], bh[p][3], sbuf + T_BH + off);
            LDMATRIX_X4(bl[p][0], bl[p][1], bl[p][2], bl[p][3], sbuf + T_BL + off);
        }
#pragma unroll
        for (int mi = 0; mi < 4; mi++)
#pragma unroll
            for (int ni = 0; ni < 4; ni++) {
                const int p = ni >> 1, s = (ni & 1) * 2;
                MMA_BF16(acc[mi][ni], ah[mi], bh[p][s], bh[p][s + 1]);  // hi*hi
                MMA_BF16(acc[mi][ni], ah[mi], bl[p][s], bl[p][s + 1]);  // hi*lo
                MMA_BF16(acc[mi][ni], al[mi], bh[p][s], bh[p][s + 1]);  // lo*hi
            }
    }
}

// ---------------------------------------------------------------------------
// Fused feature convert + initial charge.
// One warp per row: convert 1024 fp32 -> bf16 hi/lo and dot with charge_w.
__global__ __launch_bounds__(256) void convert_feat_charge_kernel(
    const float* __restrict__ f, const float* __restrict__ cw, const float* __restrict__ cb)
{
    const int row = blockIdx.x * 8 + (threadIdx.x >> 5);
    const int lane = threadIdx.x & 31;
    const float4* fr = (const float4*)(f + (size_t)row * Ff);
    const float4* cwv = (const float4*)cw;
    __nv_bfloat162* ph = (__nv_bfloat162*)(g_feat_hi + (size_t)row * Ff);
    __nv_bfloat162* pl = (__nv_bfloat162*)(g_feat_lo + (size_t)row * Ff);

    float dot = 0.0f;
#pragma unroll
    for (int u = 0; u < 8; u++) {
        int i = lane + u * 32;                 // float4 index within row
        float4 v = fr[i];
        float4 w = cwv[i];
        dot = fmaf(v.x, w.x, dot); dot = fmaf(v.y, w.y, dot);
        dot = fmaf(v.z, w.z, dot); dot = fmaf(v.w, w.w, dot);
        __nv_bfloat16 h0 = __float2bfloat16(v.x), h1 = __float2bfloat16(v.y);
        __nv_bfloat16 h2 = __float2bfloat16(v.z), h3 = __float2bfloat16(v.w);
        ph[2 * i]     = __halves2bfloat162(h0, h1);
        ph[2 * i + 1] = __halves2bfloat162(h2, h3);
        pl[2 * i]     = __halves2bfloat162(
            __float2bfloat16(v.x - __bfloat162float(h0)),
            __float2bfloat16(v.y - __bfloat162float(h1)));
        pl[2 * i + 1] = __halves2bfloat162(
            __float2bfloat16(v.z - __bfloat162float(h2)),
            __float2bfloat16(v.w - __bfloat162float(h3)));
    }
#pragma unroll
    for (int o = 16; o > 0; o >>= 1) dot += __shfl_xor_sync(0xFFFFFFFFu, dot, o);
    if (lane == 0) g_c0[row] = 1.0f / (1.0f + __expf(-(dot + cb[0])));
}

// ---------------------------------------------------------------------------
// transpose + split W (1024x128 -> 128x1024); blockIdx.y: 0=Wq, 1=Wk.
// Also zeroes g_received and g_cpack (folded pass).
__global__ void convert_W_kernel(const float* __restrict__ Wq, const float* __restrict__ Wk) {
    const float* W = (blockIdx.y == 0) ? Wq : Wk;
    int idx = blockIdx.x * blockDim.x + threadIdx.x;    // 0..131071
    int e = idx >> 10, fidx = idx & 1023;
    float x = W[(size_t)fidx * De + e];
    __nv_bfloat16 h = __float2bfloat16(x);
    g_WT_hi[blockIdx.y][idx] = h;
    g_WT_lo[blockIdx.y][idx] = __float2bfloat16(x - __bfloat162float(h));
    if (blockIdx.y == 0 && idx < 8 * NROWS) {
        if (idx < 4 * NROWS) g_received[idx] = 0.0f;
        else ((float*)g_cpack)[idx - 4 * NROWS] = 0.0f;
    }
}

// ---------------------------------------------------------------------------
// Projection GEMM: [128x1024] x [1024x128]^T(K-major); grid (64, 2).
// 3-stage cp.async pipeline, one __syncthreads per K-chunk.
__global__ __launch_bounds__(256, 1) void proj_mma_kernel() {
    extern __shared__ __align__(1024) char smem[];
    const int tid = threadIdx.x;
    const int y = blockIdx.y;
    const int mBase = blockIdx.x * 128;
    uint32_t sb = smem_u32(smem);

    const __nv_bfloat16* Ah = g_feat_hi + (size_t)mBase * Ff;
    const __nv_bfloat16* Al = g_feat_lo + (size_t)mBase * Ff;
    const __nv_bfloat16* Bh = g_WT_hi[y];
    const __nv_bfloat16* Bl = g_WT_lo[y];

    float acc[4][4][4];
#pragma unroll
    for (int mi = 0; mi < 4; mi++)
#pragma unroll
        for (int ni = 0; ni < 4; ni++)
#pragma unroll
            for (int k = 0; k < 4; k++) acc[mi][ni][k] = 0.0f;

    const int CHUNKS = 16;
    issue_chunk(sb + 0 * BUF_BYTES, Ah, Al, Ff, Bh, Bl, Ff, 0, tid);
    issue_chunk(sb + 1 * BUF_BYTES, Ah, Al, Ff, Bh, Bl, Ff, 1, tid);

#pragma unroll 1
    for (int c = 0; c < CHUNKS; c++) {
        if (c < CHUNKS - 1) { CP_WAIT1(); } else { CP_WAIT0(); }
        __syncthreads();                       // all warps done with buf[(c+2)%3]
        if (c + 2 < CHUNKS) {
            int buf = (c + 2) % 3;
            issue_chunk(sb + buf * BUF_BYTES, Ah, Al, Ff, Bh, Bl, Ff, c + 2, tid);
        }
        compute_chunk(sb + (c % 3) * BUF_BYTES, tid, acc);
    }

    const int lane = tid & 31, wid = tid >> 5;
    const int wm = wid & 1, wn = wid >> 1;
    const int g = lane >> 2, t2 = (lane & 3) * 2;
    __nv_bfloat16* ph = g_QK_hi[y];
    __nv_bfloat16* pl = g_QK_lo[y];
#pragma unroll
    for (int mi = 0; mi < 4; mi++)
#pragma unroll
        for (int ni = 0; ni < 4; ni++) {
            const int cc = wn * 32 + ni * 8 + t2;
#pragma unroll
            for (int half = 0; half < 2; half++) {
                const int rr = mBase + wm * 64 + mi * 16 + g + half * 8;
                float v0 = acc[mi][ni][half * 2], v1 = acc[mi][ni][half * 2 + 1];
                __nv_bfloat16 h0 = __float2bfloat16(v0), h1 = __float2bfloat16(v1);
                __nv_bfloat16 l0 = __float2bfloat16(v0 - __bfloat162float(h0));
                __nv_bfloat16 l1 = __float2bfloat16(v1 - __bfloat162float(h1));
                *(__nv_bfloat162*)(ph + (size_t)rr * De + cc) = __halves2bfloat162(h0, h1);
                *(__nv_bfloat162*)(pl + (size_t)rr * De + cc) = __halves2bfloat162(l0, l1);
            }
        }
}

// ---------------------------------------------------------------------------
// compat GEMM: base[b,i,j] = Q_i.K_j / sqrt(128) + ls/max(|i-j|,1); grid (16,16,4).
// Whole K=128 resident in smem: one wait, one sync, two chunk computes.
__global__ __launch_bounds__(256, 1) void compat_mma_kernel(const float* __restrict__ ls_p) {
    extern __shared__ __align__(1024) char smem[];
    const int tid = threadIdx.x;
    const int b = blockIdx.z;
    const int iBase = blockIdx.y * 128, jBase = blockIdx.x * 128;
    uint32_t sb = smem_u32(smem);

    const __nv_bfloat16* Ah = g_QK_hi[0] + (size_t)(b * Nn + iBase) * De;
    const __nv_bfloat16* Al = g_QK_lo[0] + (size_t)(b * Nn + iBase) * De;
    const __nv_bfloat16* Bh = g_QK_hi[1] + (size_t)(b * Nn + jBase) * De;
    const __nv_bfloat16* Bl = g_QK_lo[1] + (size_t)(b * Nn + jBase) * De;

    issue_chunk(sb + 0 * BUF_BYTES, Ah, Al, De, Bh, Bl, De, 0, tid);
    issue_chunk(sb + 1 * BUF_BYTES, Ah, Al, De, Bh, Bl, De, 1, tid);

    float acc[4][4][4];
#pragma unroll
    for (int mi = 0; mi < 4; mi++)
#pragma unroll
        for (int ni = 0; ni < 4; ni++)
#pragma unroll
            for (int k = 0; k < 4; k++) acc[mi][ni][k] = 0.0f;

    CP_WAIT0();
    __syncthreads();
    compute_chunk(sb + 0 * BUF_BYTES, tid, acc);
    compute_chunk(sb + 1 * BUF_BYTES, tid, acc);

    const float ls = *ls_p;
    const float rsqrtD = 0.08838834764831845f;  // 1/sqrt(128)
    const int lane = tid & 31, wid = tid >> 5;
    const int wm = wid & 1, wn = wid >> 1;
    const int g = lane >> 2, t2 = (lane & 3) * 2;
#pragma unroll
    for (int mi = 0; mi < 4; mi++)
#pragma unroll
        for (int ni = 0; ni < 4; ni++) {
            const int col = jBase + wn * 32 + ni * 8 + t2;
#pragma unroll
            for (int half = 0; half < 2; half++) {
                const int row = iBase + wm * 64 + mi * 16 + g + half * 8;
                float d0 = fmaxf(fabsf((float)(row - col)), 1.0f);
                float d1 = fmaxf(fabsf((float)(row - col - 1)), 1.0f);
                float2 v;
                v.x = acc[mi][ni][half * 2]     * rsqrtD + __fdividef(ls, d0);
                v.y = acc[mi][ni][half * 2 + 1] * rsqrtD + __fdividef(ls, d1);
                *(float2*)(g_base + ((size_t)(b * Nn + row)) * Nn + col) = v;
            }
        }
}

// ---------------------------------------------------------------------------
// Softmax pass: logits = base * (1 + ss * dot4(c_i, c_j)); g_cpack zero-padded.
template<bool WRITE_OUT>
__global__ __launch_bounds__(256) void softmax_pass_kernel(
    int s, float* __restrict__ out, const float* __restrict__ ss_p)
{
    __shared__ float s_red[2][8];
    const int b = blockIdx.y;
    const int rowBase = blockIdx.x * 32;
    const int tid = threadIdx.x, lane = tid & 31, wid = tid >> 5;
    const float ss = *ss_p;
    const int j0 = tid * 8;

    float4 cj[8];
#pragma unroll
    for (int t = 0; t < 8; t++) cj[t] = g_cpack[b * Nn + j0 + t];

    float col[8];
#pragma unroll
    for (int t = 0; t < 8; t++) col[t] = 0.0f;

    for (int r = 0; r < 32; r++) {
        const int i = rowBase + r;
        float4 ci = g_cpack[b * Nn + i];
        float cx = ci.x * ss, cy = ci.y * ss, cz = ci.z * ss, cw = ci.w * ss;

        const float4* brow = (const float4*)(g_base + ((size_t)(b * Nn + i)) * Nn + j0);
        float4 b0 = brow[0], b1 = brow[1];
        float bb[8] = {b0.x, b0.y, b0.z, b0.w, b1.x, b1.y, b1.z, b1.w};

        float lv[8];
        float lsum = 0.0f;
#pragma unroll
        for (int t = 0; t < 8; t++) {
            float m = 1.0f;
            m = fmaf(cx, cj[t].x, m);
            m = fmaf(cy, cj[t].y, m);
            m = fmaf(cz, cj[t].z, m);
            m = fmaf(cw, cj[t].w, m);
            float e = __expf(bb[t] * m);
            lv[t] = e;
            lsum += e;
        }
#pragma unroll
        for (int o = 16; o > 0; o >>= 1) lsum += __shfl_xor_sync(0xFFFFFFFFu, lsum, o);
        if (lane == 0) s_red[r & 1][wid] = lsum;
        __syncthreads();
        float tot = s_red[r & 1][0];
#pragma unroll
        for (int w = 1; w < 8; w++) tot += s_red[r & 1][w];
        float inv = __fdividef(1.0f, tot);

        if (WRITE_OUT) {
            float4* orow = (float4*)(out + ((size_t)(b * Nn + i)) * Nn + j0);
            orow[0] = make_float4(lv[0] * inv, lv[1] * inv, lv[2] * inv, lv[3] * inv);
            orow[1] = make_float4(lv[4] * inv, lv[5] * inv, lv[6] * inv, lv[7] * inv);
        } else {
#pragma unroll
            for (int t = 0; t < 8; t++) col[t] = fmaf(lv[t], inv, col[t]);
        }
    }
    if (!WRITE_OUT) {
        float* recv = g_received + (size_t)s * NROWS + b * Nn + j0;
#pragma unroll
        for (int t = 0; t < 8; t++) atomicAdd(&recv[t], col[t]);
    }
}

// ---------------------------------------------------------------------------
// charge update: c^{s+1} = c^s * (1 - decay * sigmoid(received_s - 1))
__global__ void charge_update_kernel(int s, const float* __restrict__ decay_p) {
    int r = blockIdx.x * blockDim.x + threadIdx.x;
    if (r >= NROWS) return;
    float recv = g_received[(size_t)s * NROWS + r];
    float prev = (s == 0) ? g_c0[r] : ((float*)&g_cpack[r])[s - 1];
    float sig = 1.0f / (1.0f + __expf(-(recv - 1.0f)));
    ((float*)&g_cpack[r])[s] = prev * (1.0f - (*decay_p) * sig);
}

// ---------------------------------------------------------------------------
extern "C" void kernel_launch(void* const* d_in, const int* in_sizes, int n_in,
                              void* d_out, int out_size)
{
    const float* features = (const float*)d_in[0];
    const float* W_q      = (const float*)d_in[1];
    const float* W_k      = (const float*)d_in[2];
    const float* charge_w = (const float*)d_in[3];
    const float* charge_b = (const float*)d_in[4];
    const float* ls_p     = (const float*)d_in[5];
    const float* ss_p     = (const float*)d_in[6];
    const float* decay_p  = (const float*)d_in[7];
    float* out = (float*)d_out;

    static bool attr_set = false;
    if (!attr_set) {
        cudaFuncSetAttribute(proj_mma_kernel,   cudaFuncAttributeMaxDynamicSharedMemorySize, PROJ_SMEM);
        cudaFuncSetAttribute(compat_mma_kernel, cudaFuncAttributeMaxDynamicSharedMemorySize, COMPAT_SMEM);
        attr_set = true;
    }

    convert_W_kernel<<<dim3((De * Ff) / 256, 2), 256>>>(W_q, W_k);
    convert_feat_charge_kernel<<<NROWS / 8, 256>>>(features, charge_w, charge_b);

    proj_mma_kernel<<<dim3(NROWS / 128, 2), 256, PROJ_SMEM>>>();
    compat_mma_kernel<<<dim3(Nn / 128, Nn / 128, Bb), 256, COMPAT_SMEM>>>(ls_p);

    dim3 sgrid(Nn / 32, Bb);
    for (int s = 0; s < 4; s++) {
        softmax_pass_kernel<false><<<sgrid, 256>>>(s, nullptr, ss_p);
        charge_update_kernel<<<NROWS / 256, 256>>>(s, decay_p);
    }
    softmax_pass_kernel<true><<<sgrid, 256>>>(0, out, ss_p);
}